// round 8
// baseline (speedup 1.0000x reference)
#include <cuda_runtime.h>
#include <cstdint>

// out[b,c,h,w] = x[b,c,2h,2w] * 0.5f     (Haar DWT subband sum collapses to this)
// x:  [16, 64, 512, 512] fp32,  out: [16, 64, 256, 256] fp32
//
// Warp-coalesced geometry (same as R4/R5):
//   pair index p in [0, 33'554'432):  out float2 index = p
//   pair  = p & 127          (128 float2 per output row)
//   orow  = (p >> 7) & 255
//   bc    = p >> 15
//   input float4 index = bc*65536 + orow*256 + pair   (even input row 2*orow)
//
// Persistent kernel: 1184 CTAs (148 SM x 8), grid-stride over chunks of
// 1024 pairs; within each chunk MLP=4 (thread t handles base+t+{0,256,512,768}).
// Loads: __ldcs (streaming, zero reuse). Stores: default policy so the
// write-back L2 batches the write stream to DRAM.

__device__ __forceinline__ long long pair_to_in_idx(unsigned p)
{
    unsigned pair = p & 127u;
    unsigned orow = (p >> 7) & 255u;
    unsigned bc   = p >> 15;
    return ((long long)bc << 16) + ((long long)orow << 8) + pair;
}

__global__ __launch_bounds__(256) void haar_sum_kernel(
    const float4* __restrict__ x, float2* __restrict__ out,
    unsigned n_chunks)   // chunks of 1024 pairs
{
    const unsigned stride = gridDim.x;   // chunks advance by grid size

    for (unsigned c = blockIdx.x; c < n_chunks; c += stride) {
        unsigned i0 = c * 1024u + threadIdx.x;
        unsigned i1 = i0 + 256u;
        unsigned i2 = i0 + 512u;
        unsigned i3 = i0 + 768u;

        long long a0 = pair_to_in_idx(i0);
        long long a1 = pair_to_in_idx(i1);
        long long a2 = pair_to_in_idx(i2);
        long long a3 = pair_to_in_idx(i3);

        // four independent streaming loads in flight
        float4 v0 = __ldcs(&x[a0]);
        float4 v1 = __ldcs(&x[a1]);
        float4 v2 = __ldcs(&x[a2]);
        float4 v3 = __ldcs(&x[a3]);

        float2 o0, o1, o2, o3;
        o0.x = v0.x * 0.5f;  o0.y = v0.z * 0.5f;
        o1.x = v1.x * 0.5f;  o1.y = v1.z * 0.5f;
        o2.x = v2.x * 0.5f;  o2.y = v2.z * 0.5f;
        o3.x = v3.x * 0.5f;  o3.y = v3.z * 0.5f;

        // default store policy: let write-back L2 batch the write stream
        out[i0] = o0;
        out[i1] = o1;
        out[i2] = o2;
        out[i3] = o3;
    }
}

extern "C" void kernel_launch(void* const* d_in, const int* in_sizes, int n_in,
                              void* d_out, int out_size)
{
    const float4* x = (const float4*)d_in[0];
    float2* out     = (float2*)d_out;

    // out_size = 67,108,864 floats -> 33,554,432 pairs -> 32768 chunks of 1024
    unsigned n_chunks = (unsigned)((long long)out_size / 2 / 1024);

    const unsigned blocks = 148u * 8u;   // one full wave at occupancy 8
    haar_sum_kernel<<<blocks, 256>>>(x, out, n_chunks);
}

// round 9
// speedup vs baseline: 1.1182x; 1.1182x over previous
#include <cuda_runtime.h>
#include <cstdint>

// out[b,c,h,w] = x[b,c,2h,2w] * 0.5f     (Haar DWT subband sum collapses to this)
// x:  [16, 64, 512, 512] fp32,  out: [16, 64, 256, 256] fp32
//
// Flat grid (proven superior to persistent loop in R7), MLP=4 (proven
// saturating in R5/R6), fully warp-coalesced:
//   pair index p in [0, 33'554'432):  out float2 index = p
//   pair = p & 127, orow = (p>>7) & 255, bc = p >> 15
//   input float4 index = bc*65536 + orow*256 + pair   (even input row 2*orow)
//
// Each block owns 1024 aligned consecutive pairs = 8 output rows of one
// (b,c) image; thread t handles pairs base+t+{0,256,512,768}. Because the
// block is 1024-aligned, bc is constant and orow advances by 2 per step:
//   in_idx_k = in_idx_0 + 512*k      (one decomposition, immediate offsets)
// Every LDG.128 is 512B-contiguous per warp; every STG.64 coalesced.

__global__ __launch_bounds__(256) void haar_sum_kernel(
    const float4* __restrict__ x, float2* __restrict__ out)
{
    const unsigned i0 = blockIdx.x * 1024u + threadIdx.x;

    // single index decomposition
    const unsigned pair = i0 & 127u;
    const unsigned orow = (i0 >> 7) & 255u;
    const unsigned bc   = i0 >> 15;
    const long long a0  = ((long long)bc << 16) + ((long long)orow << 8) + pair;

    // four independent streaming loads, addresses a0 + 512k (rows r, r+2, r+4, r+6)
    float4 v0 = __ldcs(&x[a0]);
    float4 v1 = __ldcs(&x[a0 +  512]);
    float4 v2 = __ldcs(&x[a0 + 1024]);
    float4 v3 = __ldcs(&x[a0 + 1536]);

    float2 o0, o1, o2, o3;
    o0.x = v0.x * 0.5f;  o0.y = v0.z * 0.5f;
    o1.x = v1.x * 0.5f;  o1.y = v1.z * 0.5f;
    o2.x = v2.x * 0.5f;  o2.y = v2.z * 0.5f;
    o3.x = v3.x * 0.5f;  o3.y = v3.z * 0.5f;

    __stcs(&out[i0],        o0);
    __stcs(&out[i0 + 256u], o1);
    __stcs(&out[i0 + 512u], o2);
    __stcs(&out[i0 + 768u], o3);
}

extern "C" void kernel_launch(void* const* d_in, const int* in_sizes, int n_in,
                              void* d_out, int out_size)
{
    const float4* x = (const float4*)d_in[0];
    float2* out     = (float2*)d_out;

    // out_size = 67,108,864 floats -> 33,554,432 pairs -> 1024 pairs per block
    long long n_pairs = (long long)out_size / 2;
    long long blocks  = n_pairs / 1024;                // 32768

    haar_sum_kernel<<<(unsigned)blocks, 256>>>(x, out);
}